// round 5
// baseline (speedup 1.0000x reference)
#include <cuda_runtime.h>

// ---------------- complex float helpers ----------------
struct cf { float x, y; };
__device__ __forceinline__ cf cmul(cf a, cf b) { return {a.x*b.x - a.y*b.y, a.x*b.y + a.y*b.x}; }
__device__ __forceinline__ cf cadd(cf a, cf b) { return {a.x + b.x, a.y + b.y}; }
__device__ __forceinline__ cf conjc(cf a)      { return {a.x, -a.y}; }

// Compute the 9 bilinear coefficients from q_weights (fp32, MUFU sincos).
// Coefficients: [const, C0, S0, C1, C0C1, S0C1, S1, C0S1, S0S1]
// __noinline__ is load-bearing: keeps its ~100-register body out of the main
// kernel's allocation (R4 showed inlining it costs 102 regs -> 22% occupancy).
__device__ __noinline__ void compute_coefs(const float* __restrict__ qw,
                                           float* __restrict__ coef) {
    cf U[4][4];
#pragma unroll
    for (int r = 0; r < 4; r++)
#pragma unroll
        for (int c = 0; c < 4; c++)
            U[r][c] = { (r == c) ? 1.0f : 0.0f, 0.0f };

    // Row permutation of combined CNOT(0,1) then CNOT(1,0): new[r] = old[perm[r]]
    const int perm[4] = {0, 2, 3, 1};

#pragma unroll
    for (int l = 0; l < 3; l++) {
        cf R[2][2][2];
#pragma unroll
        for (int w = 0; w < 2; w++) {
            float phi = qw[l*6 + w*3 + 0];
            float th  = qw[l*6 + w*3 + 1];
            float om  = qw[l*6 + w*3 + 2];
            float c, s, sp, cp, sm, cm;
            __sincosf(0.5f * th, &s, &c);
            __sincosf(0.5f * (phi + om), &sp, &cp);
            __sincosf(0.5f * (phi - om), &sm, &cm);
            cf ep = { cp, -sp };  // e^{-i(phi+om)/2}
            cf em = { cm,  sm };  // e^{+i(phi-om)/2}
            R[w][0][0] = { ep.x*c,  ep.y*c };
            R[w][0][1] = {-em.x*s, -em.y*s };
            R[w][1][0] = { em.x*s, -em.y*s };   // conj(em)*s
            R[w][1][1] = { ep.x*c, -ep.y*c };   // conj(ep)*c
        }
        // A = U0 (kron) U1 on index n = 2*i + k
        cf A[4][4];
#pragma unroll
        for (int i = 0; i < 2; i++)
#pragma unroll
            for (int k = 0; k < 2; k++)
#pragma unroll
                for (int j = 0; j < 2; j++)
#pragma unroll
                    for (int m = 0; m < 2; m++)
                        A[2*i + k][2*j + m] = cmul(R[0][i][j], R[1][k][m]);
        // U = (CNOT10*CNOT01*A) * U   (CNOTs = row permutation of A)
        cf NU[4][4];
#pragma unroll
        for (int r = 0; r < 4; r++)
#pragma unroll
            for (int c = 0; c < 4; c++) {
                cf acc = {0.0f, 0.0f};
#pragma unroll
                for (int t = 0; t < 4; t++) acc = cadd(acc, cmul(A[perm[r]][t], U[t][c]));
                NU[r][c] = acc;
            }
#pragma unroll
        for (int r = 0; r < 4; r++)
#pragma unroll
            for (int c = 0; c < 4; c++)
                U[r][c] = NU[r][c];
    }

    // M = U^dagger (Z x I) U ; Z x I = diag(1,1,-1,-1)
    const float z[4] = {1.0f, 1.0f, -1.0f, -1.0f};
    cf M[4][4];
#pragma unroll
    for (int j = 0; j < 4; j++)
#pragma unroll
        for (int k = 0; k < 4; k++) {
            cf acc = {0.0f, 0.0f};
#pragma unroll
            for (int n = 0; n < 4; n++) {
                cf t = cmul(conjc(U[n][j]), U[n][k]);
                acc = cadd(acc, (cf){t.x * z[n], t.y * z[n]});
            }
            M[j][k] = acc;
        }

    // Q = Re( conj(d_j) d_k M_jk ), d = (1, -i, -i, -1)
    cf d[4] = { {1,0}, {0,-1}, {0,-1}, {-1,0} };
    float Q[4][4];
#pragma unroll
    for (int j = 0; j < 4; j++)
#pragma unroll
        for (int k = 0; k < 4; k++) {
            cf t = cmul(cmul(conjc(d[j]), d[k]), M[j][k]);
            Q[j][k] = t.x;
        }

    // Collapse quadratic form in (c0c1, c0s1, s0c1, s0s1) to bilinear form in
    // (1, cos x0, sin x0) x (1, cos x1, sin x1) via double-angle identities.
    coef[0] = (Q[0][0] + Q[1][1] + Q[2][2] + Q[3][3]) * 0.25f;  // 1
    coef[1] = (Q[0][0] + Q[1][1] - Q[2][2] - Q[3][3]) * 0.25f;  // C0
    coef[2] = (Q[0][2] + Q[1][3]) * 0.5f;                        // S0
    coef[3] = (Q[0][0] - Q[1][1] + Q[2][2] - Q[3][3]) * 0.25f;  // C1
    coef[4] = (Q[0][0] - Q[1][1] - Q[2][2] + Q[3][3]) * 0.25f;  // C0*C1
    coef[5] = (Q[0][2] - Q[1][3]) * 0.5f;                        // S0*C1
    coef[6] = (Q[0][1] + Q[2][3]) * 0.5f;                        // S1
    coef[7] = (Q[0][1] - Q[2][3]) * 0.5f;                        // C0*S1
    coef[8] = (Q[0][3] + Q[1][2]) * 0.5f;                        // S0*S1
}

// ---------------- fused kernel: 4 elements per thread ----------------
__device__ __forceinline__ float eval_elem(float x0, float x1, const float* c) {
    float s0, c0, s1, c1;
    __sincosf(x0, &s0, &c0);
    __sincosf(x1, &s1, &c1);
    float t0 = fmaf(c[1], c0, fmaf(c[2], s0, c[0]));
    float t1 = fmaf(c[4], c0, fmaf(c[5], s0, c[3]));
    float t2 = fmaf(c[7], c0, fmaf(c[8], s0, c[6]));
    return fmaf(c1, t1, fmaf(s1, t2, t0));
}

__global__ void __launch_bounds__(256, 6)
qlayer_fused(const float4* __restrict__ x, const float* __restrict__ qw,
             float2* __restrict__ out, int n2) {
    __shared__ float sc[9];

    int i = blockIdx.x * blockDim.x + threadIdx.x;

    // Front-batch both 128-bit loads BEFORE the barrier — the per-block
    // coefficient chain on thread 0 overlaps this DRAM latency.
    float4 a = make_float4(0.f, 0.f, 0.f, 0.f);
    float4 b = make_float4(0.f, 0.f, 0.f, 0.f);
    bool active = (i < n2);
    if (active) {
        a = __ldg(&x[2*i]);
        b = __ldg(&x[2*i + 1]);
    }

    // One thread per block (redundantly across blocks) derives the 9 coefs.
    if (threadIdx.x == 0) {
        compute_coefs(qw, sc);
    }
    __syncthreads();

    float c[9];
#pragma unroll
    for (int j = 0; j < 9; j++) c[j] = sc[j];

    if (active) {
        float4 r;
        r.x = eval_elem(a.x, a.y, c);
        r.y = eval_elem(a.z, a.w, c);
        r.z = eval_elem(b.x, b.y, c);
        r.w = eval_elem(b.z, b.w, c);
        // one 128-bit store
        *reinterpret_cast<float4*>(&out[2*i]) = r;
    }
}

// Tail kernel for out_size not divisible by 4 (not hit for B=4M, defensive).
__global__ void qlayer_tail(const float2* __restrict__ x, const float* __restrict__ qw,
                            float* __restrict__ out, int start, int n) {
    __shared__ float sc[9];
    if (threadIdx.x == 0) compute_coefs(qw, sc);
    __syncthreads();
    int i = start + blockIdx.x * blockDim.x + threadIdx.x;
    if (i >= n) return;
    float2 v = x[i];
    out[i] = eval_elem(v.x, v.y, sc);
}

extern "C" void kernel_launch(void* const* d_in, const int* in_sizes, int n_in,
                              void* d_out, int out_size) {
    const float* x  = (const float*)d_in[0];   // [B, 2]
    const float* qw = (const float*)d_in[1];   // [3, 2, 3]

    int n4 = out_size / 4;                     // threads needed (4 elem each)
    int threads = 256;
    int blocks = (n4 + threads - 1) / threads;
    if (blocks > 0)
        qlayer_fused<<<blocks, threads>>>((const float4*)x, qw, (float2*)d_out, n4);

    int done = n4 * 4;
    if (done < out_size) {
        int rem = out_size - done;
        qlayer_tail<<<(rem + 127) / 128, 128>>>((const float2*)x, qw, (float*)d_out,
                                                done, out_size);
    }
}

// round 6
// speedup vs baseline: 4.1179x; 4.1179x over previous
#include <cuda_runtime.h>

// ---------------- complex float helpers (setup only, 1 thread) ----------------
struct cf { float x, y; };
__device__ __forceinline__ cf cmul(cf a, cf b) { return {a.x*b.x - a.y*b.y, a.x*b.y + a.y*b.x}; }
__device__ __forceinline__ cf cadd(cf a, cf b) { return {a.x + b.x, a.y + b.y}; }
__device__ __forceinline__ cf conjc(cf a)      { return {a.x, -a.y}; }

// 9 bilinear coefficients: [const, C0, S0, C1, C0C1, S0C1, S1, C0S1, S0S1]
__device__ float g_coef[9];

// Build the batch-independent 4x4 unitary from q_weights, reduce to the
// 9-coefficient real bilinear form. fp32 + MUFU sincos; error ~1e-6 << 1e-3.
__global__ void setup_kernel(const float* __restrict__ qw) {
    if (threadIdx.x != 0 || blockIdx.x != 0) return;

    cf U[4][4];
#pragma unroll
    for (int r = 0; r < 4; r++)
#pragma unroll
        for (int c = 0; c < 4; c++)
            U[r][c] = { (r == c) ? 1.0f : 0.0f, 0.0f };

    // Row permutation of combined CNOT(0,1) then CNOT(1,0): new[r] = old[perm[r]]
    const int perm[4] = {0, 2, 3, 1};

#pragma unroll
    for (int l = 0; l < 3; l++) {
        cf R[2][2][2];
#pragma unroll
        for (int w = 0; w < 2; w++) {
            float phi = qw[l*6 + w*3 + 0];
            float th  = qw[l*6 + w*3 + 1];
            float om  = qw[l*6 + w*3 + 2];
            float c, s, sp, cp, sm, cm;
            __sincosf(0.5f * th, &s, &c);
            __sincosf(0.5f * (phi + om), &sp, &cp);
            __sincosf(0.5f * (phi - om), &sm, &cm);
            cf ep = { cp, -sp };  // e^{-i(phi+om)/2}
            cf em = { cm,  sm };  // e^{+i(phi-om)/2}
            R[w][0][0] = { ep.x*c,  ep.y*c };
            R[w][0][1] = {-em.x*s, -em.y*s };
            R[w][1][0] = { em.x*s, -em.y*s };   // conj(em)*s
            R[w][1][1] = { ep.x*c, -ep.y*c };   // conj(ep)*c
        }
        // A = U0 (kron) U1 on index n = 2*i + k
        cf A[4][4];
#pragma unroll
        for (int i = 0; i < 2; i++)
#pragma unroll
            for (int k = 0; k < 2; k++)
#pragma unroll
                for (int j = 0; j < 2; j++)
#pragma unroll
                    for (int m = 0; m < 2; m++)
                        A[2*i + k][2*j + m] = cmul(R[0][i][j], R[1][k][m]);
        // U = (CNOT10*CNOT01*A) * U   (CNOTs = row permutation of A)
        cf NU[4][4];
#pragma unroll
        for (int r = 0; r < 4; r++)
#pragma unroll
            for (int c = 0; c < 4; c++) {
                cf acc = {0.0f, 0.0f};
#pragma unroll
                for (int t = 0; t < 4; t++) acc = cadd(acc, cmul(A[perm[r]][t], U[t][c]));
                NU[r][c] = acc;
            }
#pragma unroll
        for (int r = 0; r < 4; r++)
#pragma unroll
            for (int c = 0; c < 4; c++)
                U[r][c] = NU[r][c];
    }

    // M = U^dagger (Z x I) U ; Z x I = diag(1,1,-1,-1)
    const float z[4] = {1.0f, 1.0f, -1.0f, -1.0f};
    cf M[4][4];
#pragma unroll
    for (int j = 0; j < 4; j++)
#pragma unroll
        for (int k = 0; k < 4; k++) {
            cf acc = {0.0f, 0.0f};
#pragma unroll
            for (int n = 0; n < 4; n++) {
                cf t = cmul(conjc(U[n][j]), U[n][k]);
                acc = cadd(acc, (cf){t.x * z[n], t.y * z[n]});
            }
            M[j][k] = acc;
        }

    // Q = Re( conj(d_j) d_k M_jk ), d = (1, -i, -i, -1)
    cf d[4] = { {1,0}, {0,-1}, {0,-1}, {-1,0} };
    float Q[4][4];
#pragma unroll
    for (int j = 0; j < 4; j++)
#pragma unroll
        for (int k = 0; k < 4; k++) {
            cf t = cmul(cmul(conjc(d[j]), d[k]), M[j][k]);
            Q[j][k] = t.x;
        }

    // Collapse quadratic form in (c0c1, c0s1, s0c1, s0s1) to bilinear form in
    // (1, cos x0, sin x0) x (1, cos x1, sin x1) via double-angle identities.
    g_coef[0] = (Q[0][0] + Q[1][1] + Q[2][2] + Q[3][3]) * 0.25f;  // 1
    g_coef[1] = (Q[0][0] + Q[1][1] - Q[2][2] - Q[3][3]) * 0.25f;  // C0
    g_coef[2] = (Q[0][2] + Q[1][3]) * 0.5f;                        // S0
    g_coef[3] = (Q[0][0] - Q[1][1] + Q[2][2] - Q[3][3]) * 0.25f;  // C1
    g_coef[4] = (Q[0][0] - Q[1][1] - Q[2][2] + Q[3][3]) * 0.25f;  // C0*C1
    g_coef[5] = (Q[0][2] - Q[1][3]) * 0.5f;                        // S0*C1
    g_coef[6] = (Q[0][1] + Q[2][3]) * 0.5f;                        // S1
    g_coef[7] = (Q[0][1] - Q[2][3]) * 0.5f;                        // C0*S1
    g_coef[8] = (Q[0][3] + Q[1][2]) * 0.5f;                        // S0*S1
}

// ---------------- main streaming kernel: 4 elements per thread ----------------
__device__ __forceinline__ float eval_elem(float x0, float x1, const float* c) {
    float s0, c0, s1, c1;
    __sincosf(x0, &s0, &c0);
    __sincosf(x1, &s1, &c1);
    float t0 = fmaf(c[1], c0, fmaf(c[2], s0, c[0]));
    float t1 = fmaf(c[4], c0, fmaf(c[5], s0, c[3]));
    float t2 = fmaf(c[7], c0, fmaf(c[8], s0, c[6]));
    return fmaf(c1, t1, fmaf(s1, t2, t0));
}

__global__ void __launch_bounds__(256)
qlayer_kernel(const float4* __restrict__ x, float4* __restrict__ out, int n4) {
    int i = blockIdx.x * blockDim.x + threadIdx.x;
    if (i >= n4) return;
    // Front-batch both 128-bit loads (independent of the setup kernel's
    // output) so their DRAM latency overlaps the PDL grid-dependency wait.
    float4 a = __ldg(&x[2*i]);
    float4 b = __ldg(&x[2*i + 1]);

#if __CUDA_ARCH__ >= 900
    cudaGridDependencySynchronize();   // wait for setup_kernel (PDL)
#endif

    float c[9];
#pragma unroll
    for (int j = 0; j < 9; j++) c[j] = g_coef[j];

    float4 r;
    r.x = eval_elem(a.x, a.y, c);
    r.y = eval_elem(a.z, a.w, c);
    r.z = eval_elem(b.x, b.y, c);
    r.w = eval_elem(b.z, b.w, c);
    out[i] = r;
}

// Tail kernel for out_size not divisible by 4 (not hit for B=4M, defensive).
__global__ void qlayer_tail(const float2* __restrict__ x, float* __restrict__ out,
                            int start, int n) {
    int i = start + blockIdx.x * blockDim.x + threadIdx.x;
    if (i >= n) return;
    float c[9];
#pragma unroll
    for (int j = 0; j < 9; j++) c[j] = g_coef[j];
    float2 v = x[i];
    out[i] = eval_elem(v.x, v.y, c);
}

extern "C" void kernel_launch(void* const* d_in, const int* in_sizes, int n_in,
                              void* d_out, int out_size) {
    const float* x  = (const float*)d_in[0];   // [B, 2]
    const float* qw = (const float*)d_in[1];   // [3, 2, 3]

    setup_kernel<<<1, 1>>>(qw);

    int n4 = out_size / 4;                     // 4 elements per thread
    int threads = 256;
    int blocks = (n4 + threads - 1) / threads;

    if (blocks > 0) {
        // Programmatic dependent launch: start qlayer_kernel while setup_kernel
        // is still running; the device-side grid sync enforces the dependency.
        cudaLaunchConfig_t cfg = {};
        cfg.gridDim  = dim3(blocks, 1, 1);
        cfg.blockDim = dim3(threads, 1, 1);
        cfg.dynamicSmemBytes = 0;
        cfg.stream = 0;
        cudaLaunchAttribute attrs[1];
        attrs[0].id = cudaLaunchAttributeProgrammaticStreamSerialization;
        attrs[0].val.programmaticStreamSerializationAllowed = 1;
        cfg.attrs = attrs;
        cfg.numAttrs = 1;
        cudaLaunchKernelEx(&cfg, qlayer_kernel,
                           (const float4*)x, (float4*)d_out, n4);
    }

    int done = n4 * 4;
    if (done < out_size) {
        int rem = out_size - done;
        qlayer_tail<<<(rem + 127) / 128, 128>>>((const float2*)x, (float*)d_out,
                                                done, out_size);
    }
}